// round 5
// baseline (speedup 1.0000x reference)
#include <cuda_runtime.h>
#include <math.h>

// Problem constants
#define BATCH 64
#define SEQ   512
#define HID   1024
#define EMB   256
#define NCHAR 128

// Persistent-kernel geometry
#define GRID     128     // 4 batch-tiles x 32 j-tiles, 1 CTA/SM, < 148 SMs -> all resident wave 1
#define NTHREADS 128     // 4 warps = 1 per SMSP
#define BT       16      // batch rows per CTA
#define JT       32      // hidden rows per CTA

#define SH_STRIDE 20     // padded h-tile row stride (floats) -> conflict-free transpose staging
#define SMEM_FLOATS (HID*JT + HID*SH_STRIDE)
#define SMEM_BYTES  (SMEM_FLOATS * 4)

// Device-global scratch (no allocations allowed)
__device__ float g_U[NCHAR * HID];          // U = embeddings @ W_ih^T  (128 x 1024)
__device__ float g_h[2][BATCH * HID];       // ping-pong hidden state
__device__ unsigned g_count = 0;            // barrier arrival counter (self-resetting)
__device__ volatile unsigned g_sense = 0;   // barrier sense (even barrier count/launch -> returns to 0)

// ---------------------------------------------------------------------------
// Grid barrier: sense reversal. State (g_count=0, g_sense=0) is restored at
// kernel end provided the number of barriers per launch is EVEN (it is: 514).
// ---------------------------------------------------------------------------
__device__ __forceinline__ void grid_barrier(unsigned s) {
    __syncthreads();
    if (threadIdx.x == 0) {
        __threadfence();  // make this CTA's global writes visible before arrival
        if (atomicAdd(&g_count, 1u) == (unsigned)GRID - 1u) {
            g_count = 0;
            __threadfence();
            g_sense = s;
        } else {
            while (g_sense != s) { }
            __threadfence();
        }
    }
    __syncthreads();
}

// ---------------------------------------------------------------------------
// Kernel 0: U[c][j] = sum_e emb[c][e] * W_ih[j][e]
// One warp computes 32 outputs; lanes split the E=256 reduction (coalesced).
// ---------------------------------------------------------------------------
__global__ void u_kernel(const float* __restrict__ emb, const float* __restrict__ wih) {
    int gt   = blockIdx.x * blockDim.x + threadIdx.x;
    int warp = gt >> 5;
    int lane = gt & 31;
    int e0   = lane * 8;
    for (int i = 0; i < 32; i++) {
        int o = warp * 32 + i;          // 131072 outputs total
        int c = o >> 10;
        int j = o & 1023;
        const float4* ep = (const float4*)(emb + c * EMB + e0);
        const float4* wp = (const float4*)(wih + j * EMB + e0);
        float4 e1 = __ldg(ep),     e2 = __ldg(ep + 1);
        float4 w1 = __ldg(wp),     w2 = __ldg(wp + 1);
        float acc = e1.x*w1.x + e1.y*w1.y + e1.z*w1.z + e1.w*w1.w
                  + e2.x*w2.x + e2.y*w2.y + e2.z*w2.z + e2.w*w2.w;
        acc += __shfl_xor_sync(0xffffffffu, acc, 16);
        acc += __shfl_xor_sync(0xffffffffu, acc, 8);
        acc += __shfl_xor_sync(0xffffffffu, acc, 4);
        acc += __shfl_xor_sync(0xffffffffu, acc, 2);
        acc += __shfl_xor_sync(0xffffffffu, acc, 1);
        if (lane == 0) g_U[c * HID + j] = acc;
    }
}

// ---------------------------------------------------------------------------
// Persistent RNN scan kernel.
// CTA (tb, tj): batches [tb*16, tb*16+16), hidden rows [tj*32, tj*32+32).
// W_hh slice lives in SMEM transposed [k][jj] for the whole kernel.
// Per step: stage h tile to SMEM [k][bb] (stride 20 pad, conflict-free),
// compute 512 dot products with 4b x 4j register tiles and k-split 4,
// shuffle-reduce, add U[t[b,s]], tanh, write ping-pong global h, grid barrier.
// ---------------------------------------------------------------------------
__global__ void __launch_bounds__(NTHREADS, 1) rnn_kernel(
    const int*   __restrict__ tids,
    const float* __restrict__ whh,
    const float* __restrict__ h0,
    const float* __restrict__ wproj,
    const float* __restrict__ bproj,
    float*       __restrict__ out)
{
    extern __shared__ float smem[];
    float* sW = smem;              // [1024][32]  W_hh slice, transposed
    float* sH = smem + HID * JT;   // [1024][20]  h tile, transposed, padded

    const int tid = threadIdx.x;
    const int cta = blockIdx.x;
    const int tb  = cta >> 5;      // 0..3
    const int tj  = cta & 31;      // 0..31
    const int b0  = tb * BT;
    const int j0  = tj * JT;

    // --- one-time: load W_hh slice transposed into SMEM (coalesced LDG) ---
    for (int idx = tid; idx < JT * HID; idx += NTHREADS) {
        int jj = idx >> 10;
        int k  = idx & 1023;
        sW[k * JT + jj] = whh[(j0 + jj) * HID + k];
    }
    // --- one-time: init h ping buffer with broadcast h0 (this CTA's tile) ---
    for (int idx = tid; idx < BT * JT; idx += NTHREADS) {
        int bb = idx >> 5;
        int jj = idx & 31;
        g_h[0][(b0 + bb) * HID + (j0 + jj)] = h0[j0 + jj];
    }

    unsigned bsense = 0;
    bsense ^= 1; grid_barrier(bsense);              // barrier #1

    const int w  = tid >> 5;   // warp = batch group (4 batches each)
    const int l  = tid & 31;
    const int jg = l & 7;      // j group (4 j's each)
    const int ks = l >> 3;     // k slice (256 k's each)
    const int kbase = ks * 256;

    const float* pW = sW + jg * 4;
    const float* pH = sH + w * 4;

    for (int s = 0; s < SEQ; s++) {
        const int cur = s & 1;
        const int nxt = cur ^ 1;

        // ---- stage h tile: sH[k][bb] = h[b0+bb][k], bypassing L1 (.cg) ----
        {
            const float* hb = g_h[cur];
            const int bb  = tid & 15;
            const int kq0 = tid >> 4;    // 0..7
            const float* hrow = hb + (b0 + bb) * HID;
            float* shb = sH + bb;
            #pragma unroll 8
            for (int it = 0; it < 32; it++) {
                int k = (it * 8 + kq0) * 4;
                float4 v = __ldcg((const float4*)(hrow + k));
                shb[(k + 0) * SH_STRIDE] = v.x;
                shb[(k + 1) * SH_STRIDE] = v.y;
                shb[(k + 2) * SH_STRIDE] = v.z;
                shb[(k + 3) * SH_STRIDE] = v.w;
            }
        }
        __syncthreads();

        // ---- main 4x4 register-tiled partial GEMM over this lane's k slice ----
        float acc[4][4];
        #pragma unroll
        for (int i = 0; i < 4; i++)
            #pragma unroll
            for (int m = 0; m < 4; m++) acc[i][m] = 0.0f;

        #pragma unroll 4
        for (int kk = 0; kk < 256; kk++) {
            const int k = kbase + kk;
            float4 wv = *(const float4*)(pW + k * JT);         // 4 j's (conflict-free)
            float4 hv = *(const float4*)(pH + k * SH_STRIDE);  // 4 b's (warp broadcast)
            float ha[4] = {hv.x, hv.y, hv.z, hv.w};
            float wa[4] = {wv.x, wv.y, wv.z, wv.w};
            #pragma unroll
            for (int i = 0; i < 4; i++)
                #pragma unroll
                for (int m = 0; m < 4; m++)
                    acc[i][m] = fmaf(ha[i], wa[m], acc[i][m]);
        }

        // ---- reduce the 4 k-slices (lanes differ in bits 3,4) ----
        #pragma unroll
        for (int i = 0; i < 4; i++)
            #pragma unroll
            for (int m = 0; m < 4; m++) {
                acc[i][m] += __shfl_xor_sync(0xffffffffu, acc[i][m], 8);
                acc[i][m] += __shfl_xor_sync(0xffffffffu, acc[i][m], 16);
            }

        // ---- epilogue: lane handles batch row i == ks -> 4 outputs ----
        float r0 = 0.f, r1 = 0.f, r2 = 0.f, r3 = 0.f;
        #pragma unroll
        for (int i = 0; i < 4; i++)
            if (ks == i) { r0 = acc[i][0]; r1 = acc[i][1]; r2 = acc[i][2]; r3 = acc[i][3]; }

        const int b = b0 + w * 4 + ks;
        const int c = tids[b * SEQ + s];
        float4 uv = *(const float4*)(g_U + c * HID + j0 + jg * 4);
        float4 hn;
        hn.x = tanhf(r0 + uv.x);
        hn.y = tanhf(r1 + uv.y);
        hn.z = tanhf(r2 + uv.z);
        hn.w = tanhf(r3 + uv.w);
        *(float4*)(g_h[nxt] + b * HID + j0 + jg * 4) = hn;

        bsense ^= 1; grid_barrier(bsense);          // barriers #2..#513
    }

    // ---- final projection: out[b][c] = h_final[b] . W_proj[c] + b_proj[c] ----
    // After s = 511 the final h is in g_h[0]. CTA covers 16 b x 4 chars.
    if (tid < 64) {
        const int bb = tid >> 2;
        const int cc = tid & 3;
        const int b  = b0 + bb;
        const int c  = tj * 4 + cc;
        const float* hp = g_h[0] + b * HID;
        const float* wp = wproj + c * HID;
        float acc2 = 0.0f;
        #pragma unroll 4
        for (int k = 0; k < HID; k += 4) {
            float4 hv = __ldcg((const float4*)(hp + k));
            float4 wv = *(const float4*)(wp + k);
            acc2 += hv.x*wv.x + hv.y*wv.y + hv.z*wv.z + hv.w*wv.w;
        }
        out[b * NCHAR + c] = acc2 + bproj[c];
    }

    bsense ^= 1; grid_barrier(bsense);              // barrier #514 (even total -> g_sense back to 0)
}

// ---------------------------------------------------------------------------
// Launch: two kernels, graph-capturable, no allocations, no syncs.
// Inputs (metadata order): t, embeddings, W_ih, W_hh, h0, W_proj, b_proj.
// ---------------------------------------------------------------------------
extern "C" void kernel_launch(void* const* d_in, const int* in_sizes, int n_in,
                              void* d_out, int out_size)
{
    const int*   t     = (const int*)  d_in[0];
    const float* emb   = (const float*)d_in[1];
    const float* wih   = (const float*)d_in[2];
    const float* whh   = (const float*)d_in[3];
    const float* h0    = (const float*)d_in[4];
    const float* wproj = (const float*)d_in[5];
    const float* bproj = (const float*)d_in[6];
    float*       out   = (float*)d_out;

    cudaFuncSetAttribute(rnn_kernel, cudaFuncAttributeMaxDynamicSharedMemorySize, SMEM_BYTES);

    u_kernel<<<512, 256>>>(emb, wih);
    rnn_kernel<<<GRID, NTHREADS, SMEM_BYTES>>>(t, whh, h0, wproj, bproj, out);
}

// round 6
// speedup vs baseline: 1.2709x; 1.2709x over previous
#include <cuda_runtime.h>
#include <math.h>

// Problem constants
#define BATCH 64
#define SEQ   512
#define HID   1024
#define EMB   256
#define NCHAR 128

// Geometry: 128 persistent CTAs = 4 batch-groups (tb) x 32 j-tiles (tj).
// 256 threads = 8 warps = 2 per SMSP (latency hiding).
#define GRID     128
#define NTHREADS 256
#define BT       16      // batch rows per CTA
#define JT       32      // hidden rows per CTA

#define SH_STRIDE 20     // padded h-tile row stride (words)
#define SP_STRIDE 34     // padded partial row stride (words)

#define SW_FLOATS (HID * JT)                    // 32768
#define SH_FLOATS (HID * SH_STRIDE)             // 20480
#define SP_FLOATS (4 * 16 * SP_STRIDE)          // 2176
#define SMEM_FLOATS (SW_FLOATS + SH_FLOATS + SP_FLOATS)
#define SMEM_BYTES  (SMEM_FLOATS * 4)           // 221,696 B

typedef unsigned long long u64;

// packed f32x2 helpers (sm_100+): one SASS FFMA2 = 2 FMAs
#define FMA2(d, a, b)   asm("fma.rn.f32x2 %0, %1, %2, %0;" : "+l"(d) : "l"(a), "l"(b))
#define PACK2(d, lo, hi) asm("mov.b64 %0, {%1, %2};" : "=l"(d) : "f"(lo), "f"(hi))

// Device-global scratch
__device__ float g_U[NCHAR * HID];          // U = embeddings @ W_ih^T
__device__ float g_h[2][BATCH * HID];       // ping-pong hidden state
__device__ unsigned g_count[4];             // per-tb-group barrier counters (self-reset)
__device__ volatile unsigned g_sense[4];    // per-group sense (ends at 0: 514 barriers/launch)

// ---------------------------------------------------------------------------
// 32-CTA group barrier (sense reversal). Only CTAs sharing a batch group sync.
// ---------------------------------------------------------------------------
__device__ __forceinline__ void group_barrier(int grp, unsigned s) {
    __syncthreads();
    if (threadIdx.x == 0) {
        __threadfence();
        if (atomicAdd(&g_count[grp], 1u) == 31u) {
            g_count[grp] = 0;
            __threadfence();
            g_sense[grp] = s;
        } else {
            while (g_sense[grp] != s) { }
            __threadfence();
        }
    }
    __syncthreads();
}

// ---------------------------------------------------------------------------
// Kernel 0: U[c][j] = sum_e emb[c][e] * W_ih[j][e]
// ---------------------------------------------------------------------------
__global__ void u_kernel(const float* __restrict__ emb, const float* __restrict__ wih) {
    int gt   = blockIdx.x * blockDim.x + threadIdx.x;
    int warp = gt >> 5;
    int lane = gt & 31;
    int e0   = lane * 8;
    for (int i = 0; i < 32; i++) {
        int o = warp * 32 + i;
        int c = o >> 10;
        int j = o & 1023;
        const float4* ep = (const float4*)(emb + c * EMB + e0);
        const float4* wp = (const float4*)(wih + j * EMB + e0);
        float4 e1 = __ldg(ep),     e2 = __ldg(ep + 1);
        float4 w1 = __ldg(wp),     w2 = __ldg(wp + 1);
        float acc = e1.x*w1.x + e1.y*w1.y + e1.z*w1.z + e1.w*w1.w
                  + e2.x*w2.x + e2.y*w2.y + e2.z*w2.z + e2.w*w2.w;
        acc += __shfl_xor_sync(0xffffffffu, acc, 16);
        acc += __shfl_xor_sync(0xffffffffu, acc, 8);
        acc += __shfl_xor_sync(0xffffffffu, acc, 4);
        acc += __shfl_xor_sync(0xffffffffu, acc, 2);
        acc += __shfl_xor_sync(0xffffffffu, acc, 1);
        if (lane == 0) g_U[c * HID + j] = acc;
    }
}

// ---------------------------------------------------------------------------
// Persistent RNN scan.
// Warp w: bhalf = w&1 (8 batches), kq = w>>1 (k quarter).
// Lane l:  jg = l&7 (4 j's), ks = l>>3; lane's k = kk*16 + kq*4 + ks.
// Per lane per k: 8 batches (4 f32x2 pairs) x 4 j -> 16 FFMA2 + 8 MOV dup.
// Interleaved k -> h LDS 1 phase, w LDS 4 phases (optimal).
// ---------------------------------------------------------------------------
__global__ void __launch_bounds__(NTHREADS, 1) rnn_kernel(
    const int*   __restrict__ tids,
    const float* __restrict__ whh,
    const float* __restrict__ h0,
    const float* __restrict__ wproj,
    const float* __restrict__ bproj,
    float*       __restrict__ out)
{
    extern __shared__ float smem[];
    float* sW = smem;                         // [1024][32]   W slice, transposed
    float* sH = smem + SW_FLOATS;             // [1024][20]   h tile, transposed, padded
    float* sP = smem + SW_FLOATS + SH_FLOATS; // [4][16][34]  cross-warp partials

    const int tid = threadIdx.x;
    const int cta = blockIdx.x;
    const int tb  = cta >> 5;      // 0..3 (barrier group)
    const int tj  = cta & 31;      // 0..31
    const int b0  = tb * BT;
    const int j0  = tj * JT;

    // one-time: W_hh slice transposed into SMEM
    for (int idx = tid; idx < JT * HID; idx += NTHREADS) {
        int jj = idx >> 10;
        int k  = idx & 1023;
        sW[k * JT + jj] = whh[(j0 + jj) * HID + k];
    }
    // one-time: init h ping buffer (this CTA's tile)
    for (int idx = tid; idx < BT * JT; idx += NTHREADS) {
        int bb = idx >> 5;
        int jj = idx & 31;
        g_h[0][(b0 + bb) * HID + (j0 + jj)] = h0[j0 + jj];
    }

    unsigned bsense = 0;
    bsense ^= 1; group_barrier(tb, bsense);          // barrier #1

    const int w     = tid >> 5;
    const int l     = tid & 31;
    const int bhalf = w & 1;       // 8-batch half
    const int kq    = w >> 1;      // 0..3
    const int jg    = l & 7;       // 4 j's
    const int ks    = l >> 3;      // 0..3
    const int klane = kq * 4 + ks;

    // staging assignment: thread -> (bb, kq8)
    const int st_bb  = tid & 15;
    const int st_kq8 = tid >> 4;   // 0..15

    // combine assignment: thread -> (bpg, jc)
    const int jc  = tid & 31;
    const int bpg = tid >> 5;      // 0..7
    const int cbh = bpg >> 2;
    const int cbp = bpg & 3;
    const int cg  = cbh * 8 + (jc >> 2);
    const int cbase = cbp * 8 + (jc & 3) * 2;
    const int cb0 = b0 + cbh * 8 + cbp * 2;

    for (int s = 0; s < SEQ; s++) {
        const int cur = s & 1;
        const int nxt = cur ^ 1;

        // ---- stage h tile: sH[k][bb] = h[b0+bb][k], L1-bypassed ----
        {
            const float* hrow = g_h[cur] + (b0 + st_bb) * HID;
            float* shb = sH + st_bb;
            #pragma unroll 4
            for (int it = 0; it < 16; it++) {
                int k = (it * 16 + st_kq8) * 4;
                float4 v = __ldcg((const float4*)(hrow + k));
                shb[(k + 0) * SH_STRIDE] = v.x;
                shb[(k + 1) * SH_STRIDE] = v.y;
                shb[(k + 2) * SH_STRIDE] = v.z;
                shb[(k + 3) * SH_STRIDE] = v.w;
            }
        }
        __syncthreads();

        // ---- packed f32x2 partial GEMM: 8b x 4j per lane, 64 k's ----
        u64 acc[4][4];
        #pragma unroll
        for (int bp = 0; bp < 4; bp++)
            #pragma unroll
            for (int j = 0; j < 4; j++) acc[bp][j] = 0ull;

        const float* hptr = sH + klane * SH_STRIDE + bhalf * 8;
        const float* wptr = sW + klane * JT + jg * 4;

        #pragma unroll 4
        for (int kk = 0; kk < 64; kk++) {
            float4 hA = *(const float4*)hptr;
            float4 hB = *(const float4*)(hptr + 4);
            float4 wv = *(const float4*)wptr;
            hptr += 16 * SH_STRIDE;
            wptr += 16 * JT;

            u64 hp[4], wd[4];
            PACK2(hp[0], hA.x, hA.y);  PACK2(hp[1], hA.z, hA.w);
            PACK2(hp[2], hB.x, hB.y);  PACK2(hp[3], hB.z, hB.w);
            PACK2(wd[0], wv.x, wv.x);  PACK2(wd[1], wv.y, wv.y);
            PACK2(wd[2], wv.z, wv.z);  PACK2(wd[3], wv.w, wv.w);

            #pragma unroll
            for (int bp = 0; bp < 4; bp++)
                #pragma unroll
                for (int j = 0; j < 4; j++)
                    FMA2(acc[bp][j], hp[bp], wd[j]);
        }

        // ---- intra-warp reduce over ks (lane bits 3,4), then stash partials ----
        #pragma unroll
        for (int bp = 0; bp < 4; bp++) {
            #pragma unroll
            for (int j = 0; j < 4; j++) {
                float lo = __uint_as_float((unsigned)(acc[bp][j] & 0xffffffffull));
                float hi = __uint_as_float((unsigned)(acc[bp][j] >> 32));
                lo += __shfl_xor_sync(0xffffffffu, lo, 8);
                hi += __shfl_xor_sync(0xffffffffu, hi, 8);
                lo += __shfl_xor_sync(0xffffffffu, lo, 16);
                hi += __shfl_xor_sync(0xffffffffu, hi, 16);
                if (ks == 0) {
                    int g = bhalf * 8 + jg;
                    *(float2*)(sP + (kq * 16 + g) * SP_STRIDE + bp * 8 + j * 2)
                        = make_float2(lo, hi);
                }
            }
        }
        __syncthreads();

        // ---- combine 4 kq partials, add U, tanh, write next h ----
        {
            float slo = 0.f, shi = 0.f;
            #pragma unroll
            for (int q = 0; q < 4; q++) {
                float2 v = *(const float2*)(sP + (q * 16 + cg) * SP_STRIDE + cbase);
                slo += v.x; shi += v.y;
            }
            int c0 = tids[cb0 * SEQ + s];
            int c1 = tids[(cb0 + 1) * SEQ + s];
            float u0 = g_U[c0 * HID + j0 + jc];
            float u1 = g_U[c1 * HID + j0 + jc];
            float hn0 = tanhf(slo + u0);
            float hn1 = tanhf(shi + u1);
            __stcg(&g_h[nxt][cb0 * HID + j0 + jc], hn0);
            __stcg(&g_h[nxt][(cb0 + 1) * HID + j0 + jc], hn1);
        }

        bsense ^= 1; group_barrier(tb, bsense);      // barriers #2..#513
    }

    // ---- final projection: out[b][c] = h_final[b] . W_proj[c] + b_proj[c] ----
    if (tid < 64) {
        const int bb = tid >> 2;
        const int cc = tid & 3;
        const int b  = b0 + bb;
        const int c  = tj * 4 + cc;
        const float* hp = g_h[0] + b * HID;
        const float* wp = wproj + c * HID;
        float acc2 = 0.0f;
        #pragma unroll 4
        for (int k = 0; k < HID; k += 4) {
            float4 hv = __ldcg((const float4*)(hp + k));
            float4 wv = *(const float4*)(wp + k);
            acc2 += hv.x*wv.x + hv.y*wv.y + hv.z*wv.z + hv.w*wv.w;
        }
        out[b * NCHAR + c] = acc2 + bproj[c];
    }

    bsense ^= 1; group_barrier(tb, bsense);          // barrier #514 (sense -> 0)
}

// ---------------------------------------------------------------------------
// Launch: graph-capturable, no allocations, no syncs.
// Inputs: t, embeddings, W_ih, W_hh, h0, W_proj, b_proj.
// ---------------------------------------------------------------------------
extern "C" void kernel_launch(void* const* d_in, const int* in_sizes, int n_in,
                              void* d_out, int out_size)
{
    const int*   t     = (const int*)  d_in[0];
    const float* emb   = (const float*)d_in[1];
    const float* wih   = (const float*)d_in[2];
    const float* whh   = (const float*)d_in[3];
    const float* h0    = (const float*)d_in[4];
    const float* wproj = (const float*)d_in[5];
    const float* bproj = (const float*)d_in[6];
    float*       out   = (float*)d_out;

    cudaFuncSetAttribute(rnn_kernel, cudaFuncAttributeMaxDynamicSharedMemorySize, SMEM_BYTES);

    u_kernel<<<512, 256>>>(emb, wih);
    rnn_kernel<<<GRID, NTHREADS, SMEM_BYTES>>>(t, whh, h0, wproj, bproj, out);
}